// round 3
// baseline (speedup 1.0000x reference)
#include <cuda_runtime.h>
#include <cuda_bf16.h>
#include <cstdint>

// Problem dims (fixed): B=8, N=2048, C=1024, D=16
#define BSZ 8
#define SEQ 2048
#define DM  1024
#define DS  16
#define TOT (BSZ * SEQ * DM)   // 16,777,216

#define LOG2E 1.4426950408889634f

// Scratch (allocation-free rule: static __device__ globals)
__device__ float g_xf[(size_t)TOT];   // conv output
__device__ float g_dt[(size_t)TOT];   // dt after sigmoid scaling

__device__ __forceinline__ float ex2f(float x) {
    float y; asm("ex2.approx.f32 %0, %1;" : "=f"(y) : "f"(x)); return y;
}
__device__ __forceinline__ float rcpf(float x) {
    float y; asm("rcp.approx.f32 %0, %1;" : "=f"(y) : "f"(x)); return y;
}

// ---------------------------------------------------------------------------
// Kernel 1: depthwise conv k=3 pad=1 along sequence dim.
// xf[b,n,c] = w0*x[b,n-1,c] + w1*x[b,n,c] + w2*x[b,n+1,c] + cb[c]
// ---------------------------------------------------------------------------
__global__ void conv_kernel(const float* __restrict__ x,
                            const float* __restrict__ cw,
                            const float* __restrict__ cb)
{
    size_t idx = (size_t)blockIdx.x * blockDim.x + threadIdx.x;
    if (idx >= (size_t)TOT) return;
    int c = (int)(idx & (DM - 1));
    int n = (int)((idx >> 10) & (SEQ - 1));

    float w0 = cw[c * 3 + 0];
    float w1 = cw[c * 3 + 1];
    float w2 = cw[c * 3 + 2];

    float xm = (n > 0)       ? x[idx - DM] : 0.0f;
    float xc = x[idx];
    float xp = (n < SEQ - 1) ? x[idx + DM] : 0.0f;

    g_xf[idx] = fmaf(w0, xm, fmaf(w1, xc, fmaf(w2, xp, cb[c])));
}

// ---------------------------------------------------------------------------
// Kernel 2: dt = sigmoid(xf @ dt_w^T + dt_b) * 0.099 + 0.001
// A = g_xf [M=16384, K=1024] row-major; W = dt_w [N=1024, K=1024] row-major.
// out[m][n] = sum_k A[m][k] * W[n][k]   (both K-contiguous -> symmetric loads)
// 128x128 block tile, BK=16, 256 threads, 8x8 microtile.
// ---------------------------------------------------------------------------
#define GBM 128
#define GBN 128
#define GBK 16
#define GPAD 4   // 132-float rows, keeps 16B alignment

__global__ __launch_bounds__(256, 2)
void gemm_dt_kernel(const float* __restrict__ W, const float* __restrict__ bias)
{
    __shared__ float As[GBK][GBM + GPAD];
    __shared__ float Bs[GBK][GBN + GPAD];

    const float* A = g_xf;
    int tid = threadIdx.x;
    int bm = blockIdx.y * GBM;
    int bn = blockIdx.x * GBN;
    int ty = tid >> 4;       // 0..15
    int tx = tid & 15;       // 0..15

    float acc[8][8];
#pragma unroll
    for (int i = 0; i < 8; ++i)
#pragma unroll
        for (int j = 0; j < 8; ++j) acc[i][j] = 0.0f;

    for (int k0 = 0; k0 < DM; k0 += GBK) {
#pragma unroll
        for (int ld = 0; ld < 2; ++ld) {
            int s   = tid + ld * 256;         // 0..511
            int row = s >> 2;                 // 0..127
            int kk  = (s & 3) << 2;           // 0,4,8,12
            float4 va = *(const float4*)(A + (size_t)(bm + row) * DM + k0 + kk);
            As[kk + 0][row] = va.x; As[kk + 1][row] = va.y;
            As[kk + 2][row] = va.z; As[kk + 3][row] = va.w;
            float4 vb = *(const float4*)(W + (size_t)(bn + row) * DM + k0 + kk);
            Bs[kk + 0][row] = vb.x; Bs[kk + 1][row] = vb.y;
            Bs[kk + 2][row] = vb.z; Bs[kk + 3][row] = vb.w;
        }
        __syncthreads();

#pragma unroll
        for (int k = 0; k < GBK; ++k) {
            float a[8], b[8];
            *(float4*)(a + 0) = *(const float4*)&As[k][ty * 8 + 0];
            *(float4*)(a + 4) = *(const float4*)&As[k][ty * 8 + 4];
            *(float4*)(b + 0) = *(const float4*)&Bs[k][tx * 8 + 0];
            *(float4*)(b + 4) = *(const float4*)&Bs[k][tx * 8 + 4];
#pragma unroll
            for (int i = 0; i < 8; ++i)
#pragma unroll
                for (int j = 0; j < 8; ++j)
                    acc[i][j] = fmaf(a[i], b[j], acc[i][j]);
        }
        __syncthreads();
    }

    // Epilogue: sigmoid scaling, vectorized float4 stores
#pragma unroll
    for (int i = 0; i < 8; ++i) {
        size_t m = (size_t)(bm + ty * 8 + i);
        float v[8];
#pragma unroll
        for (int j = 0; j < 8; ++j) {
            float r   = acc[i][j] + bias[bn + tx * 8 + j];
            float e   = ex2f(-r * LOG2E);
            float sig = rcpf(1.0f + e);
            v[j] = fmaf(sig, 0.099f, 0.001f);
        }
        float* dst = g_dt + m * DM + bn + tx * 8;
        *(float4*)(dst + 0) = *(const float4*)(v + 0);
        *(float4*)(dst + 4) = *(const float4*)(v + 4);
    }
}

// ---------------------------------------------------------------------------
// Kernel 3: selective scan. One thread per (b, c) chain, D=16 states in regs.
// s_d <- exp(dt*A_d)*s_d + (dt*xf)*b_d ;  y = sum_d s_d*c_d
// exp via MUFU EX2 (overlaps FMA pipe). 4-step register prefetch pipeline
// to hide global-load latency (single warp per SMSP otherwise exposes it).
// ---------------------------------------------------------------------------
__global__ __launch_bounds__(128)
void scan_kernel(const float* __restrict__ a_log,
                 const float* __restrict__ Bm,
                 const float* __restrict__ Cm,
                 float* __restrict__ out)
{
    int bb = blockIdx.x >> 3;                       // batch 0..7
    int c  = ((blockIdx.x & 7) << 7) + threadIdx.x; // channel 0..1023

    float A2[DS], Bv[DS], Cv[DS], s[DS];
#pragma unroll
    for (int d = 0; d < DS; ++d) {
        float z  = a_log[c * DS + d];
        // softplus, numerically stable
        float sp = fmaxf(z, 0.0f) + log1pf(__expf(-fabsf(z)));
        A2[d] = -sp * LOG2E;              // pre-scaled for ex2
        Bv[d] = Bm[c * DS + d];
        Cv[d] = Cm[c * DS + d];
        s[d]  = 0.0f;
    }

    size_t base = ((size_t)bb * SEQ) * DM + c;
    const float* pdt = g_dt + base;
    const float* pxf = g_xf + base;
    float*       py  = out  + base;

    float ndt[4], nxf[4], cdt[4], cxf[4];
#pragma unroll
    for (int i = 0; i < 4; ++i) {
        ndt[i] = __ldcs(pdt + i * DM);
        nxf[i] = __ldcs(pxf + i * DM);
    }

    for (int blk = 0; blk < SEQ / 4; ++blk) {
#pragma unroll
        for (int i = 0; i < 4; ++i) { cdt[i] = ndt[i]; cxf[i] = nxf[i]; }

        if (blk < SEQ / 4 - 1) {
            const float* q1 = pdt + (size_t)(blk + 1) * 4 * DM;
            const float* q2 = pxf + (size_t)(blk + 1) * 4 * DM;
#pragma unroll
            for (int i = 0; i < 4; ++i) {
                ndt[i] = __ldcs(q1 + i * DM);
                nxf[i] = __ldcs(q2 + i * DM);
            }
        }

#pragma unroll
        for (int i = 0; i < 4; ++i) {
            float dt  = cdt[i];
            float u   = dt * cxf[i];
            float acc = 0.0f;
#pragma unroll
            for (int d = 0; d < DS; ++d) {
                float e = ex2f(dt * A2[d]);          // MUFU pipe
                s[d] = fmaf(e, s[d], u * Bv[d]);     // FMA pipe
                acc  = fmaf(s[d], Cv[d], acc);
            }
            py[(blk * 4 + i) * DM] = acc;
        }
    }
}

// ---------------------------------------------------------------------------
extern "C" void kernel_launch(void* const* d_in, const int* in_sizes, int n_in,
                              void* d_out, int out_size)
{
    const float* x      = (const float*)d_in[0];  // (8,2048,1024)
    const float* a_log  = (const float*)d_in[1];  // (1024,16)
    const float* b      = (const float*)d_in[2];  // (1024,16)
    const float* c      = (const float*)d_in[3];  // (1024,16)
    const float* dt_w   = (const float*)d_in[4];  // (1024,1024)
    const float* dt_b   = (const float*)d_in[5];  // (1024,)
    const float* conv_w = (const float*)d_in[6];  // (1024,1,3)
    const float* conv_b = (const float*)d_in[7];  // (1024,)
    float* out = (float*)d_out;                   // (8,2048,1024)

    // 1) depthwise conv -> g_xf
    conv_kernel<<<TOT / 256, 256>>>(x, conv_w, conv_b);

    // 2) dt GEMM (+sigmoid) -> g_dt   M=16384, N=1024, K=1024
    dim3 ggrid(DM / GBN, (BSZ * SEQ) / GBM);   // (8, 128)
    gemm_dt_kernel<<<ggrid, 256>>>(dt_w, dt_b);

    // 3) selective scan -> out
    scan_kernel<<<BSZ * (DM / 128), 128>>>(a_log, b, c, out);
}

// round 4
// speedup vs baseline: 1.3346x; 1.3346x over previous
#include <cuda_runtime.h>
#include <cuda_bf16.h>
#include <cstdint>

// Problem dims (fixed): B=8, N=2048, C=1024, D=16
#define BSZ 8
#define SEQ 2048
#define DM  1024
#define DS  16
#define TOT (BSZ * SEQ * DM)   // 16,777,216

#define LOG2E 1.4426950408889634f

// Scratch (allocation-free rule: static __device__ globals)
__device__ float          g_xf[(size_t)TOT];        // conv output fp32 (scan input)
__device__ float          g_dt[(size_t)TOT];        // dt after sigmoid scaling
__device__ __nv_bfloat16  g_xh[(size_t)TOT];        // hi(xf)
__device__ __nv_bfloat16  g_xl[(size_t)TOT];        // lo(xf)
__device__ __nv_bfloat16  g_wh[(size_t)DM * DM];    // hi(dt_w)
__device__ __nv_bfloat16  g_wl[(size_t)DM * DM];    // lo(dt_w)

__device__ __forceinline__ float ex2f(float x) {
    float y; asm("ex2.approx.f32 %0, %1;" : "=f"(y) : "f"(x)); return y;
}
__device__ __forceinline__ float rcpf(float x) {
    float y; asm("rcp.approx.f32 %0, %1;" : "=f"(y) : "f"(x)); return y;
}

__device__ __forceinline__ void split_bf16(float v, __nv_bfloat16& h, __nv_bfloat16& l) {
    h = __float2bfloat16(v);
    l = __float2bfloat16(v - __bfloat162float(h));
}

// ---------------------------------------------------------------------------
// Kernel 1: depthwise conv k=3 pad=1 along sequence. float4-vectorized.
// Emits fp32 xf (for scan) + bf16 hi/lo (for the tensor-core GEMM).
// ---------------------------------------------------------------------------
__global__ void conv_kernel(const float4* __restrict__ x4,
                            const float4* __restrict__ cw4,
                            const float4* __restrict__ cb4)
{
    int i4 = blockIdx.x * blockDim.x + threadIdx.x;      // 0 .. TOT/4-1
    if (i4 >= TOT / 4) return;
    int c4 = i4 & (DM / 4 - 1);                          // float4 index in channel dim
    int n  = (i4 >> 8) & (SEQ - 1);

    // weights for 4 channels: cw flat = ch*3 + k, 12 floats = 3 float4
    float4 wa = cw4[c4 * 3 + 0];   // w[0][0] w[0][1] w[0][2] w[1][0]
    float4 wb = cw4[c4 * 3 + 1];   // w[1][1] w[1][2] w[2][0] w[2][1]
    float4 wc = cw4[c4 * 3 + 2];   // w[2][2] w[3][0] w[3][1] w[3][2]
    float4 bb = cb4[c4];

    const float4 z = make_float4(0.f, 0.f, 0.f, 0.f);
    float4 xm = (n > 0)       ? x4[i4 - DM / 4] : z;
    float4 xc = x4[i4];
    float4 xp = (n < SEQ - 1) ? x4[i4 + DM / 4] : z;

    float4 y;
    y.x = fmaf(wa.x, xm.x, fmaf(wa.y, xc.x, fmaf(wa.z, xp.x, bb.x)));
    y.y = fmaf(wa.w, xm.y, fmaf(wb.x, xc.y, fmaf(wb.y, xp.y, bb.y)));
    y.z = fmaf(wb.z, xm.z, fmaf(wb.w, xc.z, fmaf(wc.x, xp.z, bb.z)));
    y.w = fmaf(wc.y, xm.w, fmaf(wc.z, xc.w, fmaf(wc.w, xp.w, bb.w)));

    ((float4*)g_xf)[i4] = y;

    __nv_bfloat16 h0, h1, h2, h3, l0, l1, l2, l3;
    split_bf16(y.x, h0, l0); split_bf16(y.y, h1, l1);
    split_bf16(y.z, h2, l2); split_bf16(y.w, h3, l3);
    __nv_bfloat162 hh01 = {h0, h1}, hh23 = {h2, h3};
    __nv_bfloat162 ll01 = {l0, l1}, ll23 = {l2, l3};
    uint2 hp, lp;
    hp.x = *(uint32_t*)&hh01; hp.y = *(uint32_t*)&hh23;
    lp.x = *(uint32_t*)&ll01; lp.y = *(uint32_t*)&ll23;
    *(uint2*)&g_xh[(size_t)i4 * 4] = hp;
    *(uint2*)&g_xl[(size_t)i4 * 4] = lp;
}

// ---------------------------------------------------------------------------
// Kernel 1b: split dt_w into bf16 hi/lo (1M elements, trivial)
// ---------------------------------------------------------------------------
__global__ void wsplit_kernel(const float4* __restrict__ w4)
{
    int i4 = blockIdx.x * blockDim.x + threadIdx.x;
    if (i4 >= DM * DM / 4) return;
    float4 v = w4[i4];
    __nv_bfloat16 h0, h1, h2, h3, l0, l1, l2, l3;
    split_bf16(v.x, h0, l0); split_bf16(v.y, h1, l1);
    split_bf16(v.z, h2, l2); split_bf16(v.w, h3, l3);
    __nv_bfloat162 hh01 = {h0, h1}, hh23 = {h2, h3};
    __nv_bfloat162 ll01 = {l0, l1}, ll23 = {l2, l3};
    uint2 hp, lp;
    hp.x = *(uint32_t*)&hh01; hp.y = *(uint32_t*)&hh23;
    lp.x = *(uint32_t*)&ll01; lp.y = *(uint32_t*)&ll23;
    *(uint2*)&g_wh[(size_t)i4 * 4] = hp;
    *(uint2*)&g_wl[(size_t)i4 * 4] = lp;
}

// ---------------------------------------------------------------------------
// Kernel 2: dt GEMM on tensor cores, bf16 3-pass hi/lo split (~fp32 accuracy).
// D[m][n] = sum_k A[m][k]*W[n][k];  A = xf (M=16384 x K=1024), W (N=1024 x K).
// Tiles: CTA 128x128x32, 8 warps each 32(M) x 64(N) via m16n8k16 mma.sync.
// SMEM rows padded to 40 bf16 (stride 20 banks -> conflict-free frag loads).
// ---------------------------------------------------------------------------
#define TBK 32
#define SPAD 40

__device__ __forceinline__ void mma_bf16(float* c, const uint32_t* a, const uint32_t* b) {
    asm volatile(
        "mma.sync.aligned.m16n8k16.row.col.f32.bf16.bf16.f32 "
        "{%0,%1,%2,%3},{%4,%5,%6,%7},{%8,%9},{%0,%1,%2,%3};"
        : "+f"(c[0]), "+f"(c[1]), "+f"(c[2]), "+f"(c[3])
        : "r"(a[0]), "r"(a[1]), "r"(a[2]), "r"(a[3]), "r"(b[0]), "r"(b[1]));
}

__global__ __launch_bounds__(256)
void gemm_dt_kernel(const float* __restrict__ bias)
{
    __shared__ __nv_bfloat16 Ah[128][SPAD];
    __shared__ __nv_bfloat16 Al[128][SPAD];
    __shared__ __nv_bfloat16 Bh[128][SPAD];
    __shared__ __nv_bfloat16 Bl[128][SPAD];

    const int tid  = threadIdx.x;
    const int lane = tid & 31;
    const int warp = tid >> 5;
    const int wm   = warp >> 1;          // 0..3 -> 32-row slices
    const int wn   = warp & 1;           // 0..1 -> 64-col slices
    const int qr   = lane >> 2;          // 0..7
    const int qc   = lane & 3;           // 0..3
    const int bm   = blockIdx.y * 128;
    const int bn   = blockIdx.x * 128;

    float acc[2][8][4];
#pragma unroll
    for (int mt = 0; mt < 2; ++mt)
#pragma unroll
        for (int nt = 0; nt < 8; ++nt)
#pragma unroll
            for (int r = 0; r < 4; ++r) acc[mt][nt][r] = 0.0f;

    for (int k0 = 0; k0 < DM; k0 += TBK) {
        // ---- fill SMEM: 128x32 bf16 per array, uint4 (8 bf16) per op ----
#pragma unroll
        for (int i = 0; i < 2; ++i) {
            int f   = tid + i * 256;          // 0..511
            int row = f >> 2;                 // 0..127
            int k8  = (f & 3) << 3;           // 0,8,16,24
            size_t ga = (size_t)(bm + row) * DM + k0 + k8;
            size_t gb = (size_t)(bn + row) * DM + k0 + k8;
            *(uint4*)&Ah[row][k8] = *(const uint4*)&g_xh[ga];
            *(uint4*)&Al[row][k8] = *(const uint4*)&g_xl[ga];
            *(uint4*)&Bh[row][k8] = *(const uint4*)&g_wh[gb];
            *(uint4*)&Bl[row][k8] = *(const uint4*)&g_wl[gb];
        }
        __syncthreads();

#pragma unroll
        for (int kst = 0; kst < TBK; kst += 16) {
            uint32_t ah[2][4], al[2][4];
#pragma unroll
            for (int mt = 0; mt < 2; ++mt) {
                int r0 = wm * 32 + mt * 16 + qr;
                int c0 = kst + qc * 2;
                ah[mt][0] = *(const uint32_t*)&Ah[r0    ][c0    ];
                ah[mt][1] = *(const uint32_t*)&Ah[r0 + 8][c0    ];
                ah[mt][2] = *(const uint32_t*)&Ah[r0    ][c0 + 8];
                ah[mt][3] = *(const uint32_t*)&Ah[r0 + 8][c0 + 8];
                al[mt][0] = *(const uint32_t*)&Al[r0    ][c0    ];
                al[mt][1] = *(const uint32_t*)&Al[r0 + 8][c0    ];
                al[mt][2] = *(const uint32_t*)&Al[r0    ][c0 + 8];
                al[mt][3] = *(const uint32_t*)&Al[r0 + 8][c0 + 8];
            }
            uint32_t bh[8][2], bl[8][2];
#pragma unroll
            for (int nt = 0; nt < 8; ++nt) {
                int nr = wn * 64 + nt * 8 + qr;
                int c0 = kst + qc * 2;
                bh[nt][0] = *(const uint32_t*)&Bh[nr][c0    ];
                bh[nt][1] = *(const uint32_t*)&Bh[nr][c0 + 8];
                bl[nt][0] = *(const uint32_t*)&Bl[nr][c0    ];
                bl[nt][1] = *(const uint32_t*)&Bl[nr][c0 + 8];
            }
#pragma unroll
            for (int mt = 0; mt < 2; ++mt)
#pragma unroll
                for (int nt = 0; nt < 8; ++nt) {
                    mma_bf16(acc[mt][nt], ah[mt], bh[nt]);   // hi*hi
                    mma_bf16(acc[mt][nt], ah[mt], bl[nt]);   // hi*lo
                    mma_bf16(acc[mt][nt], al[mt], bh[nt]);   // lo*hi
                }
        }
        __syncthreads();
    }

    // ---- epilogue: bias + sigmoid scaling, write g_dt ----
#pragma unroll
    for (int mt = 0; mt < 2; ++mt) {
#pragma unroll
        for (int nt = 0; nt < 8; ++nt) {
            int row = bm + wm * 32 + mt * 16 + qr;
            int col = bn + wn * 64 + nt * 8 + qc * 2;
            float2 bb = *(const float2*)&bias[col];
#pragma unroll
            for (int half = 0; half < 2; ++half) {
                int r = row + half * 8;
                float r0 = acc[mt][nt][half * 2 + 0] + bb.x;
                float r1 = acc[mt][nt][half * 2 + 1] + bb.y;
                float s0 = rcpf(1.0f + ex2f(-r0 * LOG2E));
                float s1 = rcpf(1.0f + ex2f(-r1 * LOG2E));
                float2 v;
                v.x = fmaf(s0, 0.099f, 0.001f);
                v.y = fmaf(s1, 0.099f, 0.001f);
                *(float2*)&g_dt[(size_t)r * DM + col] = v;
            }
        }
    }
}

// ---------------------------------------------------------------------------
// Kernel 3: selective scan. One thread per (b, c) chain, D=16 states in regs.
// s_d <- exp(dt*A_d)*s_d + (dt*xf)*b_d ;  y = sum_d s_d*c_d
// exp via MUFU EX2; 4-step register prefetch to hide global latency.
// ---------------------------------------------------------------------------
__global__ __launch_bounds__(128)
void scan_kernel(const float* __restrict__ a_log,
                 const float* __restrict__ Bm,
                 const float* __restrict__ Cm,
                 float* __restrict__ out)
{
    int bb = blockIdx.x >> 3;                       // batch 0..7
    int c  = ((blockIdx.x & 7) << 7) + threadIdx.x; // channel 0..1023

    float A2[DS], Bv[DS], Cv[DS], s[DS];
#pragma unroll
    for (int d = 0; d < DS; ++d) {
        float z  = a_log[c * DS + d];
        float sp = fmaxf(z, 0.0f) + log1pf(__expf(-fabsf(z)));  // softplus
        A2[d] = -sp * LOG2E;              // pre-scaled for ex2
        Bv[d] = Bm[c * DS + d];
        Cv[d] = Cm[c * DS + d];
        s[d]  = 0.0f;
    }

    size_t base = ((size_t)bb * SEQ) * DM + c;
    const float* pdt = g_dt + base;
    const float* pxf = g_xf + base;
    float*       py  = out  + base;

    float ndt[4], nxf[4], cdt[4], cxf[4];
#pragma unroll
    for (int i = 0; i < 4; ++i) {
        ndt[i] = __ldcs(pdt + i * DM);
        nxf[i] = __ldcs(pxf + i * DM);
    }

    for (int blk = 0; blk < SEQ / 4; ++blk) {
#pragma unroll
        for (int i = 0; i < 4; ++i) { cdt[i] = ndt[i]; cxf[i] = nxf[i]; }

        if (blk < SEQ / 4 - 1) {
            const float* q1 = pdt + (size_t)(blk + 1) * 4 * DM;
            const float* q2 = pxf + (size_t)(blk + 1) * 4 * DM;
#pragma unroll
            for (int i = 0; i < 4; ++i) {
                ndt[i] = __ldcs(q1 + i * DM);
                nxf[i] = __ldcs(q2 + i * DM);
            }
        }

#pragma unroll
        for (int i = 0; i < 4; ++i) {
            float dt  = cdt[i];
            float u   = dt * cxf[i];
            float acc = 0.0f;
#pragma unroll
            for (int d = 0; d < DS; ++d) {
                float e = ex2f(dt * A2[d]);          // MUFU pipe
                s[d] = fmaf(e, s[d], u * Bv[d]);     // FMA pipe
                acc  = fmaf(s[d], Cv[d], acc);
            }
            py[(blk * 4 + i) * DM] = acc;
        }
    }
}

// ---------------------------------------------------------------------------
extern "C" void kernel_launch(void* const* d_in, const int* in_sizes, int n_in,
                              void* d_out, int out_size)
{
    const float* x      = (const float*)d_in[0];  // (8,2048,1024)
    const float* a_log  = (const float*)d_in[1];  // (1024,16)
    const float* b      = (const float*)d_in[2];  // (1024,16)
    const float* c      = (const float*)d_in[3];  // (1024,16)
    const float* dt_w   = (const float*)d_in[4];  // (1024,1024)
    const float* dt_b   = (const float*)d_in[5];  // (1024,)
    const float* conv_w = (const float*)d_in[6];  // (1024,1,3)
    const float* conv_b = (const float*)d_in[7];  // (1024,)
    float* out = (float*)d_out;                   // (8,2048,1024)

    // 1a) split dt_w into bf16 hi/lo
    wsplit_kernel<<<(DM * DM / 4 + 255) / 256, 256>>>((const float4*)dt_w);

    // 1b) depthwise conv -> g_xf (fp32) + g_xh/g_xl (bf16 hi/lo)
    conv_kernel<<<(TOT / 4 + 255) / 256, 256>>>(
        (const float4*)x, (const float4*)conv_w, (const float4*)conv_b);

    // 2) dt GEMM (+sigmoid) -> g_dt   M=16384, N=1024, K=1024 (tensor cores)
    dim3 ggrid(DM / 128, (BSZ * SEQ) / 128);   // (8, 128)
    gemm_dt_kernel<<<ggrid, 256>>>(dt_b);

    // 3) selective scan -> out
    scan_kernel<<<BSZ * (DM / 128), 128>>>(a_log, b, c, out);
}

// round 5
// speedup vs baseline: 2.1156x; 1.5852x over previous
#include <cuda_runtime.h>
#include <cuda_bf16.h>
#include <cstdint>

// Problem dims (fixed): B=8, N=2048, C=1024, D=16
#define BSZ 8
#define SEQ 2048
#define DM  1024
#define DS  16
#define TOT (BSZ * SEQ * DM)   // 16,777,216

#define NC    16               // scan chunks
#define CHUNK (SEQ / NC)       // 128 steps per chunk

#define LOG2E 1.4426950408889634f

// Scratch (allocation-free rule: static __device__ globals)
__device__ float          g_xf[(size_t)TOT];        // conv output fp32 (scan input)
__device__ float          g_dt[(size_t)TOT];        // dt after sigmoid scaling
__device__ __nv_bfloat16  g_xh[(size_t)TOT];        // hi(xf)
__device__ __nv_bfloat16  g_xl[(size_t)TOT];        // lo(xf)
__device__ __nv_bfloat16  g_wh[(size_t)DM * DM];    // hi(dt_w)
__device__ __nv_bfloat16  g_wl[(size_t)DM * DM];    // lo(dt_w)
// chunked-scan state, layout [b][ch][d][c]  (c fastest -> coalesced)
__device__ float g_P    [(size_t)BSZ * NC * DS * DM];  // chunk decay products
__device__ float g_Sloc [(size_t)BSZ * NC * DS * DM];  // chunk-local end states
__device__ float g_sinit[(size_t)BSZ * NC * DS * DM];  // per-chunk initial states

__device__ __forceinline__ float ex2f(float x) {
    float y; asm("ex2.approx.f32 %0, %1;" : "=f"(y) : "f"(x)); return y;
}
__device__ __forceinline__ float rcpf(float x) {
    float y; asm("rcp.approx.f32 %0, %1;" : "=f"(y) : "f"(x)); return y;
}
__device__ __forceinline__ void split_bf16(float v, __nv_bfloat16& h, __nv_bfloat16& l) {
    h = __float2bfloat16(v);
    l = __float2bfloat16(v - __bfloat162float(h));
}
__device__ __forceinline__ void cp16(void* s, const void* g) {
    uint32_t sa = (uint32_t)__cvta_generic_to_shared(s);
    asm volatile("cp.async.cg.shared.global [%0], [%1], 16;" :: "r"(sa), "l"(g));
}

// ---------------------------------------------------------------------------
// Kernel 1: depthwise conv k=3 pad=1 along sequence. float4-vectorized.
// Emits fp32 xf (for scan) + bf16 hi/lo (for the tensor-core GEMM).
// ---------------------------------------------------------------------------
__global__ void conv_kernel(const float4* __restrict__ x4,
                            const float4* __restrict__ cw4,
                            const float4* __restrict__ cb4)
{
    int i4 = blockIdx.x * blockDim.x + threadIdx.x;      // 0 .. TOT/4-1
    if (i4 >= TOT / 4) return;
    int c4 = i4 & (DM / 4 - 1);
    int n  = (i4 >> 8) & (SEQ - 1);

    float4 wa = cw4[c4 * 3 + 0];
    float4 wb = cw4[c4 * 3 + 1];
    float4 wc = cw4[c4 * 3 + 2];
    float4 bb = cb4[c4];

    const float4 z = make_float4(0.f, 0.f, 0.f, 0.f);
    float4 xm = (n > 0)       ? x4[i4 - DM / 4] : z;
    float4 xc = x4[i4];
    float4 xp = (n < SEQ - 1) ? x4[i4 + DM / 4] : z;

    float4 y;
    y.x = fmaf(wa.x, xm.x, fmaf(wa.y, xc.x, fmaf(wa.z, xp.x, bb.x)));
    y.y = fmaf(wa.w, xm.y, fmaf(wb.x, xc.y, fmaf(wb.y, xp.y, bb.y)));
    y.z = fmaf(wb.z, xm.z, fmaf(wb.w, xc.z, fmaf(wc.x, xp.z, bb.z)));
    y.w = fmaf(wc.y, xm.w, fmaf(wc.z, xc.w, fmaf(wc.w, xp.w, bb.w)));

    ((float4*)g_xf)[i4] = y;

    __nv_bfloat16 h0, h1, h2, h3, l0, l1, l2, l3;
    split_bf16(y.x, h0, l0); split_bf16(y.y, h1, l1);
    split_bf16(y.z, h2, l2); split_bf16(y.w, h3, l3);
    __nv_bfloat162 hh01 = {h0, h1}, hh23 = {h2, h3};
    __nv_bfloat162 ll01 = {l0, l1}, ll23 = {l2, l3};
    uint2 hp, lp;
    hp.x = *(uint32_t*)&hh01; hp.y = *(uint32_t*)&hh23;
    lp.x = *(uint32_t*)&ll01; lp.y = *(uint32_t*)&ll23;
    *(uint2*)&g_xh[(size_t)i4 * 4] = hp;
    *(uint2*)&g_xl[(size_t)i4 * 4] = lp;
}

// ---------------------------------------------------------------------------
// Kernel 1b: split dt_w into bf16 hi/lo
// ---------------------------------------------------------------------------
__global__ void wsplit_kernel(const float4* __restrict__ w4)
{
    int i4 = blockIdx.x * blockDim.x + threadIdx.x;
    if (i4 >= DM * DM / 4) return;
    float4 v = w4[i4];
    __nv_bfloat16 h0, h1, h2, h3, l0, l1, l2, l3;
    split_bf16(v.x, h0, l0); split_bf16(v.y, h1, l1);
    split_bf16(v.z, h2, l2); split_bf16(v.w, h3, l3);
    __nv_bfloat162 hh01 = {h0, h1}, hh23 = {h2, h3};
    __nv_bfloat162 ll01 = {l0, l1}, ll23 = {l2, l3};
    uint2 hp, lp;
    hp.x = *(uint32_t*)&hh01; hp.y = *(uint32_t*)&hh23;
    lp.x = *(uint32_t*)&ll01; lp.y = *(uint32_t*)&ll23;
    *(uint2*)&g_wh[(size_t)i4 * 4] = hp;
    *(uint2*)&g_wl[(size_t)i4 * 4] = lp;
}

// ---------------------------------------------------------------------------
// Kernel 2: dt GEMM on tensor cores, bf16 3-pass hi/lo split, cp.async
// double-buffered. D[m][n] = sum_k A[m][k]*W[n][k].
// CTA 128x128x32, 8 warps x (32x64) via m16n8k16. SMEM row stride 40 bf16.
// ---------------------------------------------------------------------------
#define TBK 32
#define SPAD 40
#define PER_ARR (128 * SPAD)        // elems per tile array
#define PER_STAGE (4 * PER_ARR)     // Ah, Al, Bh, Bl
#define GEMM_SMEM (2 * PER_STAGE * 2)  // bytes: 2 stages, bf16

__device__ __forceinline__ void mma_bf16(float* c, const uint32_t* a, const uint32_t* b) {
    asm volatile(
        "mma.sync.aligned.m16n8k16.row.col.f32.bf16.bf16.f32 "
        "{%0,%1,%2,%3},{%4,%5,%6,%7},{%8,%9},{%0,%1,%2,%3};"
        : "+f"(c[0]), "+f"(c[1]), "+f"(c[2]), "+f"(c[3])
        : "r"(a[0]), "r"(a[1]), "r"(a[2]), "r"(a[3]), "r"(b[0]), "r"(b[1]));
}

__global__ __launch_bounds__(256)
void gemm_dt_kernel(const float* __restrict__ bias)
{
    extern __shared__ __nv_bfloat16 sm[];

    const int tid  = threadIdx.x;
    const int lane = tid & 31;
    const int warp = tid >> 5;
    const int wm   = warp >> 1;          // 0..3 -> 32-row slices
    const int wn   = warp & 1;           // 0..1 -> 64-col slices
    const int qr   = lane >> 2;          // 0..7
    const int qc   = lane & 3;           // 0..3
    const int bm   = blockIdx.y * 128;
    const int bn   = blockIdx.x * 128;

    float acc[2][8][4];
#pragma unroll
    for (int mt = 0; mt < 2; ++mt)
#pragma unroll
        for (int nt = 0; nt < 8; ++nt)
#pragma unroll
            for (int r = 0; r < 4; ++r) acc[mt][nt][r] = 0.0f;

    // async-load one k-stage (4 arrays x 128 x 32 bf16)
    auto load_stage = [&](int st, int k0) {
        __nv_bfloat16* base = sm + st * PER_STAGE;
#pragma unroll
        for (int i = 0; i < 2; ++i) {
            int f   = tid + i * 256;          // 0..511
            int row = f >> 2;
            int k8  = (f & 3) << 3;           // 0,8,16,24
            size_t ga = (size_t)(bm + row) * DM + k0 + k8;
            size_t gb = (size_t)(bn + row) * DM + k0 + k8;
            int so = row * SPAD + k8;
            cp16(base + 0 * PER_ARR + so, &g_xh[ga]);
            cp16(base + 1 * PER_ARR + so, &g_xl[ga]);
            cp16(base + 2 * PER_ARR + so, &g_wh[gb]);
            cp16(base + 3 * PER_ARR + so, &g_wl[gb]);
        }
        asm volatile("cp.async.commit_group;");
    };

    const int KT = DM / TBK;   // 32
    load_stage(0, 0);

    for (int kt = 0; kt < KT; ++kt) {
        asm volatile("cp.async.wait_group 0;");
        __syncthreads();                       // stage data ready, prev compute done
        if (kt + 1 < KT) load_stage((kt + 1) & 1, (kt + 1) * TBK);

        const __nv_bfloat16* Ah = sm + (kt & 1) * PER_STAGE + 0 * PER_ARR;
        const __nv_bfloat16* Al = Ah + PER_ARR;
        const __nv_bfloat16* Bh = Al + PER_ARR;
        const __nv_bfloat16* Bl = Bh + PER_ARR;

#pragma unroll
        for (int kst = 0; kst < TBK; kst += 16) {
            uint32_t ah[2][4], al[2][4];
#pragma unroll
            for (int mt = 0; mt < 2; ++mt) {
                int r0 = wm * 32 + mt * 16 + qr;
                int c0 = kst + qc * 2;
                ah[mt][0] = *(const uint32_t*)&Ah[(r0    ) * SPAD + c0    ];
                ah[mt][1] = *(const uint32_t*)&Ah[(r0 + 8) * SPAD + c0    ];
                ah[mt][2] = *(const uint32_t*)&Ah[(r0    ) * SPAD + c0 + 8];
                ah[mt][3] = *(const uint32_t*)&Ah[(r0 + 8) * SPAD + c0 + 8];
                al[mt][0] = *(const uint32_t*)&Al[(r0    ) * SPAD + c0    ];
                al[mt][1] = *(const uint32_t*)&Al[(r0 + 8) * SPAD + c0    ];
                al[mt][2] = *(const uint32_t*)&Al[(r0    ) * SPAD + c0 + 8];
                al[mt][3] = *(const uint32_t*)&Al[(r0 + 8) * SPAD + c0 + 8];
            }
            uint32_t bh[8][2], bl[8][2];
#pragma unroll
            for (int nt = 0; nt < 8; ++nt) {
                int nr = wn * 64 + nt * 8 + qr;
                int c0 = kst + qc * 2;
                bh[nt][0] = *(const uint32_t*)&Bh[nr * SPAD + c0    ];
                bh[nt][1] = *(const uint32_t*)&Bh[nr * SPAD + c0 + 8];
                bl[nt][0] = *(const uint32_t*)&Bl[nr * SPAD + c0    ];
                bl[nt][1] = *(const uint32_t*)&Bl[nr * SPAD + c0 + 8];
            }
#pragma unroll
            for (int mt = 0; mt < 2; ++mt)
#pragma unroll
                for (int nt = 0; nt < 8; ++nt) {
                    mma_bf16(acc[mt][nt], ah[mt], bh[nt]);   // hi*hi
                    mma_bf16(acc[mt][nt], ah[mt], bl[nt]);   // hi*lo
                    mma_bf16(acc[mt][nt], al[mt], bh[nt]);   // lo*hi
                }
        }
        __syncthreads();
    }

    // epilogue: bias + sigmoid scaling
#pragma unroll
    for (int mt = 0; mt < 2; ++mt) {
#pragma unroll
        for (int nt = 0; nt < 8; ++nt) {
            int row = bm + wm * 32 + mt * 16 + qr;
            int col = bn + wn * 64 + nt * 8 + qc * 2;
            float2 bb = *(const float2*)&bias[col];
#pragma unroll
            for (int half = 0; half < 2; ++half) {
                int r = row + half * 8;
                float r0 = acc[mt][nt][half * 2 + 0] + bb.x;
                float r1 = acc[mt][nt][half * 2 + 1] + bb.y;
                float s0 = rcpf(1.0f + ex2f(-r0 * LOG2E));
                float s1 = rcpf(1.0f + ex2f(-r1 * LOG2E));
                float2 v;
                v.x = fmaf(s0, 0.099f, 0.001f);
                v.y = fmaf(s1, 0.099f, 0.001f);
                *(float2*)&g_dt[(size_t)r * DM + col] = v;
            }
        }
    }
}

// ---------------------------------------------------------------------------
// Kernel 3a: chunk-local scan. One thread per (b,c,chunk).
// Computes chunk decay product P[d] and local end state S_loc[d] (s starts 0).
// ---------------------------------------------------------------------------
__global__ __launch_bounds__(128)
void scan_pass1(const float* __restrict__ a_log,
                const float* __restrict__ Bm)
{
    int bb = blockIdx.z;
    int ch = blockIdx.y;
    int c  = blockIdx.x * 128 + threadIdx.x;

    float A2[DS], Bv[DS], s[DS], P[DS];
#pragma unroll
    for (int d = 0; d < DS; ++d) {
        float z  = a_log[c * DS + d];
        float sp = fmaxf(z, 0.0f) + log1pf(__expf(-fabsf(z)));  // softplus
        A2[d] = -sp * LOG2E;
        Bv[d] = Bm[c * DS + d];
        s[d]  = 0.0f;
        P[d]  = 1.0f;
    }

    size_t base = ((size_t)bb * SEQ + (size_t)ch * CHUNK) * DM + c;
    const float* pdt = g_dt + base;
    const float* pxf = g_xf + base;

    float ndt = __ldcs(pdt), nxf = __ldcs(pxf);
    for (int t = 0; t < CHUNK; ++t) {
        float dt = ndt, xf = nxf;
        if (t + 1 < CHUNK) {
            ndt = __ldcs(pdt + (size_t)(t + 1) * DM);
            nxf = __ldcs(pxf + (size_t)(t + 1) * DM);
        }
        float u = dt * xf;
#pragma unroll
        for (int d = 0; d < DS; ++d) {
            float e = ex2f(dt * A2[d]);
            s[d] = fmaf(e, s[d], u * Bv[d]);
            P[d] *= e;
        }
    }

    size_t sb = (((size_t)bb * NC + ch) * DS) * DM + c;
#pragma unroll
    for (int d = 0; d < DS; ++d) {
        g_P   [sb + (size_t)d * DM] = P[d];
        g_Sloc[sb + (size_t)d * DM] = s[d];
    }
}

// ---------------------------------------------------------------------------
// Kernel 3b: sequential combine across chunks (tiny). One thread per (b,c).
// s_init[ch] = state entering chunk ch; s <- P[ch]*s + S_loc[ch].
// ---------------------------------------------------------------------------
__global__ __launch_bounds__(256)
void scan_pass2()
{
    int t  = blockIdx.x * blockDim.x + threadIdx.x;   // 0..8191
    int bb = t >> 10;
    int c  = t & (DM - 1);

    float s[DS];
#pragma unroll
    for (int d = 0; d < DS; ++d) s[d] = 0.0f;

    for (int ch = 0; ch < NC; ++ch) {
        size_t sb = (((size_t)bb * NC + ch) * DS) * DM + c;
#pragma unroll
        for (int d = 0; d < DS; ++d) {
            size_t ix = sb + (size_t)d * DM;
            g_sinit[ix] = s[d];
            s[d] = fmaf(g_P[ix], s[d], g_Sloc[ix]);
        }
    }
}

// ---------------------------------------------------------------------------
// Kernel 3c: final scan with correct initial state, writes y.
// ---------------------------------------------------------------------------
__global__ __launch_bounds__(128)
void scan_pass3(const float* __restrict__ a_log,
                const float* __restrict__ Bm,
                const float* __restrict__ Cm,
                float* __restrict__ out)
{
    int bb = blockIdx.z;
    int ch = blockIdx.y;
    int c  = blockIdx.x * 128 + threadIdx.x;

    float A2[DS], Bv[DS], Cv[DS], s[DS];
    size_t sb = (((size_t)bb * NC + ch) * DS) * DM + c;
#pragma unroll
    for (int d = 0; d < DS; ++d) {
        float z  = a_log[c * DS + d];
        float sp = fmaxf(z, 0.0f) + log1pf(__expf(-fabsf(z)));
        A2[d] = -sp * LOG2E;
        Bv[d] = Bm[c * DS + d];
        Cv[d] = Cm[c * DS + d];
        s[d]  = g_sinit[sb + (size_t)d * DM];
    }

    size_t base = ((size_t)bb * SEQ + (size_t)ch * CHUNK) * DM + c;
    const float* pdt = g_dt + base;
    const float* pxf = g_xf + base;
    float*       py  = out  + base;

    float ndt = __ldcs(pdt), nxf = __ldcs(pxf);
    for (int t = 0; t < CHUNK; ++t) {
        float dt = ndt, xf = nxf;
        if (t + 1 < CHUNK) {
            ndt = __ldcs(pdt + (size_t)(t + 1) * DM);
            nxf = __ldcs(pxf + (size_t)(t + 1) * DM);
        }
        float u   = dt * xf;
        float acc = 0.0f;
#pragma unroll
        for (int d = 0; d < DS; ++d) {
            float e = ex2f(dt * A2[d]);
            s[d] = fmaf(e, s[d], u * Bv[d]);
            acc  = fmaf(s[d], Cv[d], acc);
        }
        py[(size_t)t * DM] = acc;
    }
}

// ---------------------------------------------------------------------------
extern "C" void kernel_launch(void* const* d_in, const int* in_sizes, int n_in,
                              void* d_out, int out_size)
{
    const float* x      = (const float*)d_in[0];  // (8,2048,1024)
    const float* a_log  = (const float*)d_in[1];  // (1024,16)
    const float* b      = (const float*)d_in[2];  // (1024,16)
    const float* c      = (const float*)d_in[3];  // (1024,16)
    const float* dt_w   = (const float*)d_in[4];  // (1024,1024)
    const float* dt_b   = (const float*)d_in[5];  // (1024,)
    const float* conv_w = (const float*)d_in[6];  // (1024,1,3)
    const float* conv_b = (const float*)d_in[7];  // (1024,)
    float* out = (float*)d_out;                   // (8,2048,1024)

    // 1a) split dt_w into bf16 hi/lo
    wsplit_kernel<<<(DM * DM / 4 + 255) / 256, 256>>>((const float4*)dt_w);

    // 1b) depthwise conv -> g_xf (fp32) + g_xh/g_xl (bf16 hi/lo)
    conv_kernel<<<(TOT / 4 + 255) / 256, 256>>>(
        (const float4*)x, (const float4*)conv_w, (const float4*)conv_b);

    // 2) dt GEMM (+sigmoid) -> g_dt   (tensor cores, cp.async pipelined)
    cudaFuncSetAttribute(gemm_dt_kernel,
                         cudaFuncAttributeMaxDynamicSharedMemorySize, GEMM_SMEM);
    dim3 ggrid(DM / 128, (BSZ * SEQ) / 128);   // (8, 128)
    gemm_dt_kernel<<<ggrid, 256, GEMM_SMEM>>>(dt_b);

    // 3) chunked selective scan
    dim3 sgrid(DM / 128, NC, BSZ);             // (8, 16, 8) = 1024 blocks
    scan_pass1<<<sgrid, 128>>>(a_log, b);
    scan_pass2<<<(BSZ * DM) / 256, 256>>>();
    scan_pass3<<<sgrid, 128>>>(a_log, b, c, out);
}